// round 16
// baseline (speedup 1.0000x reference)
#include <cuda_runtime.h>
#include <math.h>

// ---------------- problem constants ----------------
#define B_TOTAL   16384
#define NSLOT     32
#define SDIM      64
#define HID       128
#define NKNOWN    9
#define NITER     3

#define PV_OFF    0
#define SLOTS_OFF (B_TOTAL*NKNOWN)                       // 147456
#define FREE_OFF  (B_TOTAL*NKNOWN + B_TOTAL*NSLOT*SDIM)  // 33701888

// scratch: gi[b][192] (upd == v for every slot since attn collapses to exactly 1.0)
__device__ float g_gi[(size_t)B_TOTAL * 192];

__device__ __forceinline__ float sigm_f(float x) { return 1.0f / (1.0f + __expf(-x)); }
__device__ __forceinline__ float tanh_ap(float x) {
    float y; asm("tanh.approx.f32 %0, %1;" : "=f"(y) : "f"(x)); return y;
}
__device__ __forceinline__ float sigm_t(float x) { return fmaf(tanh_ap(0.5f * x), 0.5f, 0.5f); }
__device__ __forceinline__ float gelu_f(float x) {
    float x2 = x * x;
    float inner = x * fmaf(0.044715f, x2, 1.0f);
    float t = tanh_ap(0.7978845608f * inner);
    return 0.5f * x * (1.0f + t);
}

// ================= Kernel A2: per-batch x -> LN -> v -> gi (R13 version) =================
#define SMEMA_FLOATS 36304

__global__ void __launch_bounds__(512, 1) kA2(
    const float* __restrict__ ws, const float* __restrict__ Wi, const float* __restrict__ bi,
    const float* __restrict__ g_in, const float* __restrict__ b_in,
    const float* __restrict__ Wv, const float* __restrict__ bv,
    const float* __restrict__ Wih, const float* __restrict__ bih)
{
    extern __shared__ float sa[];
    float* s_wi  = sa;
    float* s_wv  = sa + 16384;
    float* s_wih = sa + 20480;
    float* s_bi  = sa + 32768;
    float* s_bv  = sa + 32832;
    float* s_gin = sa + 32896;
    float* s_bin = sa + 32960;
    float* s_bih = sa + 33024;
    float* s_in  = sa + 33216;
    float* s_x   = sa + 35264;
    float* s_v   = sa + 35776;
    float* s_red = sa + 36288;

    int tid = threadIdx.x;
    int g = tid >> 6;
    int lane = tid & 63;
    size_t b = (size_t)blockIdx.x * 8 + g;

    for (int i = tid; i < 16384 / 4; i += 512) ((float4*)s_wi)[i]  = ((const float4*)Wi)[i];
    for (int i = tid; i < 4096 / 4;  i += 512) ((float4*)s_wv)[i]  = ((const float4*)Wv)[i];
    for (int i = tid; i < 12288 / 4; i += 512) ((float4*)s_wih)[i] = ((const float4*)Wih)[i];
    if (tid < 64)  s_bi[tid]  = bi[tid];
    if (tid >= 64  && tid < 128) s_bv[tid - 64]   = bv[tid - 64];
    if (tid >= 128 && tid < 192) s_gin[tid - 128] = g_in[tid - 128];
    if (tid >= 192 && tid < 256) s_bin[tid - 192] = b_in[tid - 192];
    if (tid >= 256 && tid < 448) s_bih[tid - 256] = bih[tid - 256];

    {
        const float4* src = (const float4*)(ws + (size_t)blockIdx.x * 8 * 256);
        for (int i = tid; i < 2048 / 4; i += 512) ((float4*)s_in)[i] = src[i];
    }
    __syncthreads();

    const float* in_g = s_in + g * 256;

    float a0 = 0.0f, a1 = 0.0f, a2 = 0.0f, a3 = 0.0f;
    #pragma unroll 4
    for (int i = 0; i < 256; i += 4) {
        a0 += in_g[i + 0] * s_wi[(i + 0) * 64 + lane];
        a1 += in_g[i + 1] * s_wi[(i + 1) * 64 + lane];
        a2 += in_g[i + 2] * s_wi[(i + 2) * 64 + lane];
        a3 += in_g[i + 3] * s_wi[(i + 3) * 64 + lane];
    }
    float acc = ((a0 + a1) + (a2 + a3)) + s_bi[lane];

    float v = acc;
    #pragma unroll
    for (int o = 16; o; o >>= 1) v += __shfl_down_sync(0xffffffffu, v, o);
    if ((lane & 31) == 0) s_red[g * 2 + (lane >> 5)] = v;
    __syncthreads();
    float mu = (s_red[g * 2] + s_red[g * 2 + 1]) * (1.0f / 64.0f);
    __syncthreads();
    float dv = acc - mu;
    float vv = dv * dv;
    #pragma unroll
    for (int o = 16; o; o >>= 1) vv += __shfl_down_sync(0xffffffffu, vv, o);
    if ((lane & 31) == 0) s_red[g * 2 + (lane >> 5)] = vv;
    __syncthreads();
    float var = (s_red[g * 2] + s_red[g * 2 + 1]) * (1.0f / 64.0f);
    float inv = rsqrtf(var + 1e-5f);
    s_x[g * 64 + lane] = dv * inv * s_gin[lane] + s_bin[lane];
    __syncthreads();

    const float* x_g = s_x + g * 64;
    float v0 = 0.0f, v1 = 0.0f, v2 = 0.0f, v3 = 0.0f;
    #pragma unroll 4
    for (int d = 0; d < 64; d += 4) {
        v0 += x_g[d + 0] * s_wv[(d + 0) * 64 + lane];
        v1 += x_g[d + 1] * s_wv[(d + 1) * 64 + lane];
        v2 += x_g[d + 2] * s_wv[(d + 2) * 64 + lane];
        v3 += x_g[d + 3] * s_wv[(d + 3) * 64 + lane];
    }
    s_v[g * 64 + lane] = ((v0 + v1) + (v2 + v3)) + s_bv[lane];
    __syncthreads();

    const float* v_g = s_v + g * 64;
    {
        float c00 = 0.0f, c01 = 0.0f, c10 = 0.0f, c11 = 0.0f, c20 = 0.0f, c21 = 0.0f;
        int j0 = lane, j1 = lane + 64, j2 = lane + 128;
        #pragma unroll 4
        for (int d = 0; d < 64; d += 2) {
            float p0 = v_g[d], p1 = v_g[d + 1];
            c00 += p0 * s_wih[d * 192 + j0];
            c01 += p1 * s_wih[(d + 1) * 192 + j0];
            c10 += p0 * s_wih[d * 192 + j1];
            c11 += p1 * s_wih[(d + 1) * 192 + j1];
            c20 += p0 * s_wih[d * 192 + j2];
            c21 += p1 * s_wih[(d + 1) * 192 + j2];
        }
        g_gi[b * 192 + j0] = (c00 + c01) + s_bih[j0];
        g_gi[b * 192 + j1] = (c10 + c11) + s_bih[j1];
        g_gi[b * 192 + j2] = (c20 + c21) + s_bih[j2];
    }
}

// ================= Kernel Z: zero free_act accumulators =================
__global__ void kZ(float* __restrict__ out)
{
    int i = threadIdx.x;
    if (i < NSLOT - NKNOWN) out[FREE_OFF + i] = 0.0f;
}

// ================= Kernel B (templated on group count NG; NT = 32*NG threads) =================
// smem layout (floats):
//   0      s_whh 12288 | 12288 s_w1 8192 | 20480 s_w2 8192 | 28672 s_bhh 192
//   28864  s_b1 128 | 28992 s_b2 64 | 29056 s_gm 64 | 29120 s_bm 64
//   29184  s_gi NG*192 | 29184+NG*192  s_prev NG*32*65
#define SMEMB_FLOATS(NG) (29184 + (NG)*192 + (NG)*32*65)

template<int NG>
__global__ void __launch_bounds__(NG * 32, 1) kB(
    int batch_base,
    const float* __restrict__ eps, const float* __restrict__ mu0, const float* __restrict__ sg0,
    const float* __restrict__ Whh, const float* __restrict__ bhh,
    const float* __restrict__ W1, const float* __restrict__ b1,
    const float* __restrict__ W2, const float* __restrict__ b2,
    const float* __restrict__ gm, const float* __restrict__ bm,
    const float* __restrict__ Wh1, const float* __restrict__ bh1,
    const float* __restrict__ Wh2, const float* __restrict__ bh2,
    float* __restrict__ out)
{
    constexpr int NT = NG * 32;
    extern __shared__ float sm[];
    float* s_whh  = sm;
    float* s_w1   = sm + 12288;
    float* s_w2   = sm + 20480;
    float* s_bhh  = sm + 28672;
    float* s_b1   = sm + 28864;
    float* s_b2   = sm + 28992;
    float* s_gm   = sm + 29056;
    float* s_bm   = sm + 29120;
    float* s_gi   = sm + 29184;
    float* s_prev = sm + 29184 + NG * 192;

    int tid = threadIdx.x;

    for (int i = tid; i < 12288 / 4; i += NT) ((float4*)s_whh)[i] = ((const float4*)Whh)[i];
    for (int i = tid; i < 8192 / 4;  i += NT) ((float4*)s_w1)[i]  = ((const float4*)W1)[i];
    for (int i = tid; i < 8192 / 4;  i += NT) ((float4*)s_w2)[i]  = ((const float4*)W2)[i];
    for (int i = tid; i < 192; i += NT) s_bhh[i] = bhh[i];
    for (int i = tid; i < 128; i += NT) s_b1[i]  = b1[i];
    for (int i = tid; i < 64;  i += NT) { s_b2[i] = b2[i]; s_gm[i] = gm[i]; s_bm[i] = bm[i]; }
    {
        size_t gbase = ((size_t)batch_base + (size_t)blockIdx.x * NG) * 192;
        for (int i = tid; i < NG * 192; i += NT) {
            if (gbase + i < (size_t)B_TOTAL * 192) {
                int r = i % 192;
                float add = (r < 128) ? bhh[r] : 0.0f;
                s_gi[i] = g_gi[gbase + i] + add;
            }
        }
    }

    int bb = tid >> 5, s = tid & 31;
    size_t b = (size_t)batch_base + (size_t)blockIdx.x * NG + bb;
    bool valid = (b < (size_t)B_TOTAL);
    int pbase = tid * 65;

    if (valid) {
        const float4* ep = (const float4*)(eps + (b * NSLOT + s) * SDIM);
        const float4* m4 = (const float4*)(mu0 + (size_t)s * SDIM);
        const float4* g4 = (const float4*)(sg0 + (size_t)s * SDIM);
        #pragma unroll
        for (int q = 0; q < 16; q++) {
            float4 e = ep[q], m = m4[q], sg = g4[q];
            s_prev[pbase + 4 * q + 0] = m.x + sg.x * e.x;
            s_prev[pbase + 4 * q + 1] = m.y + sg.y * e.y;
            s_prev[pbase + 4 * q + 2] = m.z + sg.z * e.z;
            s_prev[pbase + 4 * q + 3] = m.w + sg.w * e.w;
        }
    } else {
        #pragma unroll
        for (int q = 0; q < 64; q++) s_prev[pbase + q] = 0.0f;
    }
    __syncthreads();

    const float* gi = s_gi + bb * 192;
    float rbuf[64];

    for (int it = 0; it < NITER; ++it) {
        // ---- merged gate sweep: r, z, n per 16-wide chunk ----
        #pragma unroll
        for (int jb = 0; jb < 4; jb++) {
            float ar[16], az[16], an[16];
            #pragma unroll
            for (int jj = 0; jj < 16; jj++) {
                int j = jb * 16 + jj;
                ar[jj] = gi[j];
                az[jj] = gi[64 + j];
                an[jj] = s_bhh[128 + j];
            }
            #pragma unroll 2
            for (int d = 0; d < 64; d++) {
                float p = s_prev[pbase + d];
                const float4* wr = (const float4*)(s_whh + d * 192 + jb * 16);
                const float4* wz = (const float4*)(s_whh + d * 192 + 64 + jb * 16);
                const float4* wn = (const float4*)(s_whh + d * 192 + 128 + jb * 16);
                #pragma unroll
                for (int q = 0; q < 4; q++) {
                    float4 a = wr[q];
                    ar[4 * q + 0] += p * a.x; ar[4 * q + 1] += p * a.y;
                    ar[4 * q + 2] += p * a.z; ar[4 * q + 3] += p * a.w;
                    float4 c = wz[q];
                    az[4 * q + 0] += p * c.x; az[4 * q + 1] += p * c.y;
                    az[4 * q + 2] += p * c.z; az[4 * q + 3] += p * c.w;
                    float4 e = wn[q];
                    an[4 * q + 0] += p * e.x; an[4 * q + 1] += p * e.y;
                    an[4 * q + 2] += p * e.z; an[4 * q + 3] += p * e.w;
                }
            }
            #pragma unroll
            for (int jj = 0; jj < 16; jj++) {
                int j = jb * 16 + jj;
                float r = sigm_t(ar[jj]);
                float z = sigm_t(az[jj]);
                float n = tanh_ap(gi[128 + j] + r * an[jj]);
                float pr = s_prev[pbase + j];
                rbuf[j] = n + z * (pr - n);
            }
        }

        // ---- LayerNorm (4-way tree) + MLP residual ----
        float m0 = 0.0f, m1 = 0.0f, m2 = 0.0f, m3 = 0.0f;
        #pragma unroll
        for (int j = 0; j < 64; j += 4) {
            m0 += rbuf[j]; m1 += rbuf[j + 1]; m2 += rbuf[j + 2]; m3 += rbuf[j + 3];
        }
        float mu = ((m0 + m1) + (m2 + m3)) * (1.0f / 64.0f);
        float q0 = 0.0f, q1 = 0.0f, q2 = 0.0f, q3 = 0.0f;
        #pragma unroll
        for (int j = 0; j < 64; j += 4) {
            float d0 = rbuf[j] - mu, d1 = rbuf[j + 1] - mu, d2 = rbuf[j + 2] - mu, d3 = rbuf[j + 3] - mu;
            q0 += d0 * d0; q1 += d1 * d1; q2 += d2 * d2; q3 += d3 * d3;
        }
        float var = ((q0 + q1) + (q2 + q3)) * (1.0f / 64.0f);
        float inv = rsqrtf(var + 1e-5f);
        #pragma unroll
        for (int d = 0; d < 64; d++) s_prev[pbase + d] = (rbuf[d] - mu) * inv * s_gm[d] + s_bm[d];
        #pragma unroll
        for (int j = 0; j < 64; j++) rbuf[j] += s_b2[j];

        for (int mb = 0; mb < 8; mb++) {
            float ah[16];
            #pragma unroll
            for (int jj = 0; jj < 16; jj++) ah[jj] = s_b1[mb * 16 + jj];
            #pragma unroll 2
            for (int d = 0; d < 64; d++) {
                float p = s_prev[pbase + d];
                const float4* w = (const float4*)(s_w1 + d * 128 + mb * 16);
                #pragma unroll
                for (int q = 0; q < 4; q++) {
                    float4 a = w[q];
                    ah[4 * q + 0] += p * a.x; ah[4 * q + 1] += p * a.y;
                    ah[4 * q + 2] += p * a.z; ah[4 * q + 3] += p * a.w;
                }
            }
            #pragma unroll
            for (int jj = 0; jj < 16; jj++) {
                float g = gelu_f(ah[jj]);
                const float4* w2 = (const float4*)(s_w2 + (mb * 16 + jj) * 64);
                #pragma unroll
                for (int q = 0; q < 16; q++) {
                    float4 ww = w2[q];
                    rbuf[4 * q + 0] += g * ww.x; rbuf[4 * q + 1] += g * ww.y;
                    rbuf[4 * q + 2] += g * ww.z; rbuf[4 * q + 3] += g * ww.w;
                }
            }
        }
        #pragma unroll
        for (int d = 0; d < 64; d++) s_prev[pbase + d] = rbuf[d];
    }

    // ---- write final slots (guarded) ----
    if (valid) {
        float4* o = (float4*)(out + SLOTS_OFF + (b * NSLOT + s) * SDIM);
        #pragma unroll
        for (int q = 0; q < 16; q++)
            o[q] = make_float4(rbuf[4 * q], rbuf[4 * q + 1], rbuf[4 * q + 2], rbuf[4 * q + 3]);
    }

    // ---- free_act partial ----
    float freeval = 0.0f;
    if (valid && s >= NKNOWN) {
        float s0 = 0.0f, s1 = 0.0f, s2 = 0.0f, s3 = 0.0f;
        #pragma unroll
        for (int d = 0; d < 64; d += 4) {
            s0 += rbuf[d] * rbuf[d];     s1 += rbuf[d + 1] * rbuf[d + 1];
            s2 += rbuf[d + 2] * rbuf[d + 2]; s3 += rbuf[d + 3] * rbuf[d + 3];
        }
        freeval = sqrtf((s0 + s1) + (s2 + s3)) * (1.0f / (float)B_TOTAL);
    }

    // ---- head (overlay weight smem) + block free_act reduction ----
    __syncthreads();
    float* s_hw1  = sm;           // 18432 floats
    float* s_hb1  = sm + 18432;   // 288
    float* s_hw2  = sm + 18720;   // 288
    float* s_hb2  = sm + 19008;   // 9
    float* s_free = sm + 19072;   // 23
    for (int i = tid; i < 18432 / 4; i += NT) ((float4*)s_hw1)[i] = ((const float4*)Wh1)[i];
    for (int i = tid; i < 288; i += NT) { s_hb1[i] = bh1[i]; s_hw2[i] = Wh2[i]; }
    for (int i = tid; i < 9;  i += NT) s_hb2[i] = bh2[i];
    for (int i = tid; i < 23; i += NT) s_free[i] = 0.0f;
    __syncthreads();

    if (valid && s < NKNOWN) {
        int k = s;
        float ha[32];
        #pragma unroll
        for (int h = 0; h < 32; h++) ha[h] = s_hb1[k * 32 + h];
        #pragma unroll 2
        for (int d = 0; d < 64; d++) {
            float p = s_prev[pbase + d];
            const float4* w = (const float4*)(s_hw1 + k * 2048 + d * 32);
            #pragma unroll
            for (int q = 0; q < 8; q++) {
                float4 a = w[q];
                ha[4 * q + 0] += p * a.x; ha[4 * q + 1] += p * a.y;
                ha[4 * q + 2] += p * a.z; ha[4 * q + 3] += p * a.w;
            }
        }
        float a2 = s_hb2[k];
        #pragma unroll
        for (int h = 0; h < 32; h++) a2 += gelu_f(ha[h]) * s_hw2[k * 32 + h];
        out[PV_OFF + b * NKNOWN + k] = sigm_f(a2);
    } else if (valid && s >= NKNOWN) {
        atomicAdd(s_free + (s - NKNOWN), freeval);
    }
    __syncthreads();
    if (tid < NSLOT - NKNOWN) atomicAdd(out + FREE_OFF + tid, s_free[tid]);
}

// ================= launch =================
#define MAIN_GROUPS 12
#define MAIN_BLOCKS 1332                       // = 148 SMs x 9 full waves
#define MAIN_BATCH  (MAIN_BLOCKS * MAIN_GROUPS)  // 15984
#define TAIL_GROUPS 4
#define TAIL_BLOCKS ((B_TOTAL - MAIN_BATCH + TAIL_GROUPS - 1) / TAIL_GROUPS)  // 100

extern "C" void kernel_launch(void* const* d_in, const int* in_sizes, int n_in,
                              void* d_out, int out_size)
{
    const float* ws   = (const float*)d_in[0];
    const float* eps  = (const float*)d_in[1];
    const float* mu0  = (const float*)d_in[2];
    const float* sg0  = (const float*)d_in[3];
    const float* Wi   = (const float*)d_in[4];
    const float* bi   = (const float*)d_in[5];
    // d_in[6..9] = Wk, bk, Wq, bq : dead (attn == 1.0 exactly)
    const float* Wv   = (const float*)d_in[10];
    const float* bv   = (const float*)d_in[11];
    const float* Wih  = (const float*)d_in[12];
    const float* bih  = (const float*)d_in[13];
    const float* Whh  = (const float*)d_in[14];
    const float* bhh  = (const float*)d_in[15];
    const float* W1   = (const float*)d_in[16];
    const float* b1   = (const float*)d_in[17];
    const float* W2   = (const float*)d_in[18];
    const float* b2   = (const float*)d_in[19];
    const float* g_in = (const float*)d_in[20];
    const float* b_in = (const float*)d_in[21];
    // d_in[22..23] = g_sl, b_sl : dead
    const float* gm   = (const float*)d_in[24];
    const float* bm   = (const float*)d_in[25];
    const float* Wh1  = (const float*)d_in[26];
    const float* bh1  = (const float*)d_in[27];
    const float* Wh2  = (const float*)d_in[28];
    const float* bh2  = (const float*)d_in[29];
    float* out = (float*)d_out;

    size_t smemA  = (size_t)SMEMA_FLOATS * sizeof(float);
    size_t smemB12 = (size_t)SMEMB_FLOATS(MAIN_GROUPS) * sizeof(float);
    size_t smemB4  = (size_t)SMEMB_FLOATS(TAIL_GROUPS) * sizeof(float);
    cudaFuncSetAttribute(kA2, cudaFuncAttributeMaxDynamicSharedMemorySize, (int)smemA);
    cudaFuncSetAttribute(kB<MAIN_GROUPS>, cudaFuncAttributeMaxDynamicSharedMemorySize, (int)smemB12);
    cudaFuncSetAttribute(kB<TAIL_GROUPS>, cudaFuncAttributeMaxDynamicSharedMemorySize, (int)smemB4);

    kA2<<<B_TOTAL / 8, 512, smemA>>>(ws, Wi, bi, g_in, b_in, Wv, bv, Wih, bih);
    kZ<<<1, 32>>>(out);
    kB<MAIN_GROUPS><<<MAIN_BLOCKS, MAIN_GROUPS * 32, smemB12>>>(
        0, eps, mu0, sg0, Whh, bhh, W1, b1, W2, b2,
        gm, bm, Wh1, bh1, Wh2, bh2, out);
    kB<TAIL_GROUPS><<<TAIL_BLOCKS, TAIL_GROUPS * 32, smemB4>>>(
        MAIN_BATCH, eps, mu0, sg0, Whh, bhh, W1, b1, W2, b2,
        gm, bm, Wh1, bh1, Wh2, bh2, out);
}

// round 17
// speedup vs baseline: 1.0444x; 1.0444x over previous
#include <cuda_runtime.h>
#include <math.h>

// ---------------- problem constants ----------------
#define B_TOTAL   16384
#define NSLOT     32
#define SDIM      64
#define HID       128
#define NKNOWN    9
#define NITER     3

#define PV_OFF    0
#define SLOTS_OFF (B_TOTAL*NKNOWN)                       // 147456
#define FREE_OFF  (B_TOTAL*NKNOWN + B_TOTAL*NSLOT*SDIM)  // 33701888

// scratch: gi[b][192] (upd == v for every slot since attn collapses to exactly 1.0)
__device__ float g_gi[(size_t)B_TOTAL * 192];

__device__ __forceinline__ float sigm_f(float x) { return 1.0f / (1.0f + __expf(-x)); }
__device__ __forceinline__ float tanh_ap(float x) {
    float y; asm("tanh.approx.f32 %0, %1;" : "=f"(y) : "f"(x)); return y;
}
__device__ __forceinline__ float sigm_t(float x) { return fmaf(tanh_ap(0.5f * x), 0.5f, 0.5f); }
__device__ __forceinline__ float gelu_f(float x) {
    float x2 = x * x;
    float inner = x * fmaf(0.044715f, x2, 1.0f);
    float t = tanh_ap(0.7978845608f * inner);
    return 0.5f * x * (1.0f + t);
}

// ================= Kernel A2: per-batch x -> LN -> v -> gi =================
// R17: activation-side smem loads vectorized to LDS.128; accumulation order
// preserved exactly (bitwise-identical results to R14).
#define SMEMA_FLOATS 36304

__global__ void __launch_bounds__(512, 1) kA2(
    const float* __restrict__ ws, const float* __restrict__ Wi, const float* __restrict__ bi,
    const float* __restrict__ g_in, const float* __restrict__ b_in,
    const float* __restrict__ Wv, const float* __restrict__ bv,
    const float* __restrict__ Wih, const float* __restrict__ bih)
{
    extern __shared__ float sa[];
    float* s_wi  = sa;
    float* s_wv  = sa + 16384;
    float* s_wih = sa + 20480;
    float* s_bi  = sa + 32768;
    float* s_bv  = sa + 32832;
    float* s_gin = sa + 32896;
    float* s_bin = sa + 32960;
    float* s_bih = sa + 33024;
    float* s_in  = sa + 33216;
    float* s_x   = sa + 35264;
    float* s_v   = sa + 35776;
    float* s_red = sa + 36288;

    int tid = threadIdx.x;
    int g = tid >> 6;
    int lane = tid & 63;
    size_t b = (size_t)blockIdx.x * 8 + g;

    for (int i = tid; i < 16384 / 4; i += 512) ((float4*)s_wi)[i]  = ((const float4*)Wi)[i];
    for (int i = tid; i < 4096 / 4;  i += 512) ((float4*)s_wv)[i]  = ((const float4*)Wv)[i];
    for (int i = tid; i < 12288 / 4; i += 512) ((float4*)s_wih)[i] = ((const float4*)Wih)[i];
    if (tid < 64)  s_bi[tid]  = bi[tid];
    if (tid >= 64  && tid < 128) s_bv[tid - 64]   = bv[tid - 64];
    if (tid >= 128 && tid < 192) s_gin[tid - 128] = g_in[tid - 128];
    if (tid >= 192 && tid < 256) s_bin[tid - 192] = b_in[tid - 192];
    if (tid >= 256 && tid < 448) s_bih[tid - 256] = bih[tid - 256];

    {
        const float4* src = (const float4*)(ws + (size_t)blockIdx.x * 8 * 256);
        for (int i = tid; i < 2048 / 4; i += 512) ((float4*)s_in)[i] = src[i];
    }
    __syncthreads();

    const float4* in_g4 = (const float4*)(s_in + g * 256);

    // x[lane] = in @ Wi + bi — 4 chains, input side via LDS.128
    float a0 = 0.0f, a1 = 0.0f, a2 = 0.0f, a3 = 0.0f;
    #pragma unroll 4
    for (int i = 0; i < 64; i++) {
        float4 p = in_g4[i];
        int ib = i * 4;
        a0 += p.x * s_wi[(ib + 0) * 64 + lane];
        a1 += p.y * s_wi[(ib + 1) * 64 + lane];
        a2 += p.z * s_wi[(ib + 2) * 64 + lane];
        a3 += p.w * s_wi[(ib + 3) * 64 + lane];
    }
    float acc = ((a0 + a1) + (a2 + a3)) + s_bi[lane];

    float v = acc;
    #pragma unroll
    for (int o = 16; o; o >>= 1) v += __shfl_down_sync(0xffffffffu, v, o);
    if ((lane & 31) == 0) s_red[g * 2 + (lane >> 5)] = v;
    __syncthreads();
    float mu = (s_red[g * 2] + s_red[g * 2 + 1]) * (1.0f / 64.0f);
    __syncthreads();
    float dv = acc - mu;
    float vv = dv * dv;
    #pragma unroll
    for (int o = 16; o; o >>= 1) vv += __shfl_down_sync(0xffffffffu, vv, o);
    if ((lane & 31) == 0) s_red[g * 2 + (lane >> 5)] = vv;
    __syncthreads();
    float var = (s_red[g * 2] + s_red[g * 2 + 1]) * (1.0f / 64.0f);
    float inv = rsqrtf(var + 1e-5f);
    s_x[g * 64 + lane] = dv * inv * s_gin[lane] + s_bin[lane];
    __syncthreads();

    // v = x @ Wv + bv — 4 chains, x side via LDS.128
    const float4* x_g4 = (const float4*)(s_x + g * 64);
    float v0 = 0.0f, v1 = 0.0f, v2 = 0.0f, v3 = 0.0f;
    #pragma unroll 4
    for (int q = 0; q < 16; q++) {
        float4 p = x_g4[q];
        int d = q * 4;
        v0 += p.x * s_wv[(d + 0) * 64 + lane];
        v1 += p.y * s_wv[(d + 1) * 64 + lane];
        v2 += p.z * s_wv[(d + 2) * 64 + lane];
        v3 += p.w * s_wv[(d + 3) * 64 + lane];
    }
    s_v[g * 64 + lane] = ((v0 + v1) + (v2 + v3)) + s_bv[lane];
    __syncthreads();

    // gi = v @ W_ih + b_ih — 3 outputs x 2 chains, v side via LDS.128
    const float4* v_g4 = (const float4*)(s_v + g * 64);
    {
        float c00 = 0.0f, c01 = 0.0f, c10 = 0.0f, c11 = 0.0f, c20 = 0.0f, c21 = 0.0f;
        int j0 = lane, j1 = lane + 64, j2 = lane + 128;
        #pragma unroll 4
        for (int q = 0; q < 16; q++) {
            float4 p = v_g4[q];
            int d = q * 4;
            c00 += p.x * s_wih[(d + 0) * 192 + j0];
            c01 += p.y * s_wih[(d + 1) * 192 + j0];
            c10 += p.x * s_wih[(d + 0) * 192 + j1];
            c11 += p.y * s_wih[(d + 1) * 192 + j1];
            c20 += p.x * s_wih[(d + 0) * 192 + j2];
            c21 += p.y * s_wih[(d + 1) * 192 + j2];
            c00 += p.z * s_wih[(d + 2) * 192 + j0];
            c01 += p.w * s_wih[(d + 3) * 192 + j0];
            c10 += p.z * s_wih[(d + 2) * 192 + j1];
            c11 += p.w * s_wih[(d + 3) * 192 + j1];
            c20 += p.z * s_wih[(d + 2) * 192 + j2];
            c21 += p.w * s_wih[(d + 3) * 192 + j2];
        }
        g_gi[b * 192 + j0] = (c00 + c01) + s_bih[j0];
        g_gi[b * 192 + j1] = (c10 + c11) + s_bih[j1];
        g_gi[b * 192 + j2] = (c20 + c21) + s_bih[j2];
    }
}

// ================= Kernel Z: zero free_act accumulators =================
__global__ void kZ(float* __restrict__ out)
{
    int i = threadIdx.x;
    if (i < NSLOT - NKNOWN) out[FREE_OFF + i] = 0.0f;
}

// ================= Kernel B: 384 threads = 12 batch groups x 32 slots (R14, byte-identical) =================
#define SMEMB_FLOATS 56448
#define GROUPS_B 12

__global__ void __launch_bounds__(384, 1) kB(
    const float* __restrict__ eps, const float* __restrict__ mu0, const float* __restrict__ sg0,
    const float* __restrict__ Whh, const float* __restrict__ bhh,
    const float* __restrict__ W1, const float* __restrict__ b1,
    const float* __restrict__ W2, const float* __restrict__ b2,
    const float* __restrict__ gm, const float* __restrict__ bm,
    const float* __restrict__ Wh1, const float* __restrict__ bh1,
    const float* __restrict__ Wh2, const float* __restrict__ bh2,
    float* __restrict__ out)
{
    extern __shared__ float sm[];
    float* s_whh  = sm;
    float* s_w1   = sm + 12288;
    float* s_w2   = sm + 20480;
    float* s_bhh  = sm + 28672;
    float* s_b1   = sm + 28864;
    float* s_b2   = sm + 28992;
    float* s_gm   = sm + 29056;
    float* s_bm   = sm + 29120;
    float* s_gi   = sm + 29184;
    float* s_prev = sm + 31488;

    int tid = threadIdx.x;

    for (int i = tid; i < 12288 / 4; i += 384) ((float4*)s_whh)[i] = ((const float4*)Whh)[i];
    for (int i = tid; i < 8192 / 4;  i += 384) ((float4*)s_w1)[i]  = ((const float4*)W1)[i];
    for (int i = tid; i < 8192 / 4;  i += 384) ((float4*)s_w2)[i]  = ((const float4*)W2)[i];
    if (tid < 192) s_bhh[tid] = bhh[tid];
    if (tid < 128) s_b1[tid]  = b1[tid];
    if (tid < 64) { s_b2[tid] = b2[tid]; s_gm[tid] = gm[tid]; s_bm[tid] = bm[tid]; }
    {
        size_t gbase = (size_t)blockIdx.x * GROUPS_B * 192;
        for (int i = tid; i < GROUPS_B * 192; i += 384) {
            if (gbase + i < (size_t)B_TOTAL * 192) {
                int r = i % 192;
                float add = (r < 128) ? bhh[r] : 0.0f;
                s_gi[i] = g_gi[gbase + i] + add;
            }
        }
    }

    int bb = tid >> 5, s = tid & 31;
    size_t b = (size_t)blockIdx.x * GROUPS_B + bb;
    bool valid = (b < (size_t)B_TOTAL);
    int pbase = tid * 65;

    if (valid) {
        const float4* ep = (const float4*)(eps + (b * NSLOT + s) * SDIM);
        const float4* m4 = (const float4*)(mu0 + (size_t)s * SDIM);
        const float4* g4 = (const float4*)(sg0 + (size_t)s * SDIM);
        #pragma unroll
        for (int q = 0; q < 16; q++) {
            float4 e = ep[q], m = m4[q], sg = g4[q];
            s_prev[pbase + 4 * q + 0] = m.x + sg.x * e.x;
            s_prev[pbase + 4 * q + 1] = m.y + sg.y * e.y;
            s_prev[pbase + 4 * q + 2] = m.z + sg.z * e.z;
            s_prev[pbase + 4 * q + 3] = m.w + sg.w * e.w;
        }
    } else {
        #pragma unroll
        for (int q = 0; q < 64; q++) s_prev[pbase + q] = 0.0f;
    }
    __syncthreads();

    const float* gi = s_gi + bb * 192;
    float rbuf[64];

    for (int it = 0; it < NITER; ++it) {
        // ---- merged gate sweep: r, z, n per 16-wide chunk, one d-loop each ----
        #pragma unroll
        for (int jb = 0; jb < 4; jb++) {
            float ar[16], az[16], an[16];
            #pragma unroll
            for (int jj = 0; jj < 16; jj++) {
                int j = jb * 16 + jj;
                ar[jj] = gi[j];                    // bhh_r pre-added
                az[jj] = gi[64 + j];               // bhh_z pre-added
                an[jj] = s_bhh[128 + j];           // bhh_n stays inside r*( )
            }
            #pragma unroll 2
            for (int d = 0; d < 64; d++) {
                float p = s_prev[pbase + d];
                const float4* wr = (const float4*)(s_whh + d * 192 + jb * 16);
                const float4* wz = (const float4*)(s_whh + d * 192 + 64 + jb * 16);
                const float4* wn = (const float4*)(s_whh + d * 192 + 128 + jb * 16);
                #pragma unroll
                for (int q = 0; q < 4; q++) {
                    float4 a = wr[q];
                    ar[4 * q + 0] += p * a.x; ar[4 * q + 1] += p * a.y;
                    ar[4 * q + 2] += p * a.z; ar[4 * q + 3] += p * a.w;
                    float4 c = wz[q];
                    az[4 * q + 0] += p * c.x; az[4 * q + 1] += p * c.y;
                    az[4 * q + 2] += p * c.z; az[4 * q + 3] += p * c.w;
                    float4 e = wn[q];
                    an[4 * q + 0] += p * e.x; an[4 * q + 1] += p * e.y;
                    an[4 * q + 2] += p * e.z; an[4 * q + 3] += p * e.w;
                }
            }
            #pragma unroll
            for (int jj = 0; jj < 16; jj++) {
                int j = jb * 16 + jj;
                float r = sigm_t(ar[jj]);
                float z = sigm_t(az[jj]);
                float n = tanh_ap(gi[128 + j] + r * an[jj]);
                float pr = s_prev[pbase + j];
                rbuf[j] = (1.0f - z) * n + z * pr;
            }
        }

        // ---- LayerNorm (4-way tree) + MLP residual ----
        float m0 = 0.0f, m1 = 0.0f, m2 = 0.0f, m3 = 0.0f;
        #pragma unroll
        for (int j = 0; j < 64; j += 4) {
            m0 += rbuf[j]; m1 += rbuf[j + 1]; m2 += rbuf[j + 2]; m3 += rbuf[j + 3];
        }
        float mu = ((m0 + m1) + (m2 + m3)) * (1.0f / 64.0f);
        float q0 = 0.0f, q1 = 0.0f, q2 = 0.0f, q3 = 0.0f;
        #pragma unroll
        for (int j = 0; j < 64; j += 4) {
            float d0 = rbuf[j] - mu, d1 = rbuf[j + 1] - mu, d2 = rbuf[j + 2] - mu, d3 = rbuf[j + 3] - mu;
            q0 += d0 * d0; q1 += d1 * d1; q2 += d2 * d2; q3 += d3 * d3;
        }
        float var = ((q0 + q1) + (q2 + q3)) * (1.0f / 64.0f);
        float inv = rsqrtf(var + 1e-5f);
        #pragma unroll
        for (int d = 0; d < 64; d++) s_prev[pbase + d] = (rbuf[d] - mu) * inv * s_gm[d] + s_bm[d];
        #pragma unroll
        for (int j = 0; j < 64; j++) rbuf[j] += s_b2[j];

        for (int mb = 0; mb < 8; mb++) {
            float ah[16];
            #pragma unroll
            for (int jj = 0; jj < 16; jj++) ah[jj] = s_b1[mb * 16 + jj];
            #pragma unroll 2
            for (int d = 0; d < 64; d++) {
                float p = s_prev[pbase + d];
                const float4* w = (const float4*)(s_w1 + d * 128 + mb * 16);
                #pragma unroll
                for (int q = 0; q < 4; q++) {
                    float4 a = w[q];
                    ah[4 * q + 0] += p * a.x; ah[4 * q + 1] += p * a.y;
                    ah[4 * q + 2] += p * a.z; ah[4 * q + 3] += p * a.w;
                }
            }
            #pragma unroll
            for (int jj = 0; jj < 16; jj++) {
                float g = gelu_f(ah[jj]);
                const float4* w2 = (const float4*)(s_w2 + (mb * 16 + jj) * 64);
                #pragma unroll
                for (int q = 0; q < 16; q++) {
                    float4 ww = w2[q];
                    rbuf[4 * q + 0] += g * ww.x; rbuf[4 * q + 1] += g * ww.y;
                    rbuf[4 * q + 2] += g * ww.z; rbuf[4 * q + 3] += g * ww.w;
                }
            }
        }
        #pragma unroll
        for (int d = 0; d < 64; d++) s_prev[pbase + d] = rbuf[d];
    }

    // ---- write final slots (guarded) ----
    if (valid) {
        float4* o = (float4*)(out + SLOTS_OFF + (b * NSLOT + s) * SDIM);
        #pragma unroll
        for (int q = 0; q < 16; q++)
            o[q] = make_float4(rbuf[4 * q], rbuf[4 * q + 1], rbuf[4 * q + 2], rbuf[4 * q + 3]);
    }

    // ---- free_act partial (per thread) ----
    float freeval = 0.0f;
    if (valid && s >= NKNOWN) {
        float s0 = 0.0f, s1 = 0.0f, s2 = 0.0f, s3 = 0.0f;
        #pragma unroll
        for (int d = 0; d < 64; d += 4) {
            s0 += rbuf[d] * rbuf[d];     s1 += rbuf[d + 1] * rbuf[d + 1];
            s2 += rbuf[d + 2] * rbuf[d + 2]; s3 += rbuf[d + 3] * rbuf[d + 3];
        }
        freeval = sqrtf((s0 + s1) + (s2 + s3)) * (1.0f / (float)B_TOTAL);
    }

    // ---- head (reuse weight smem) + block-level free_act reduction ----
    __syncthreads();
    float* s_hw1  = sm;
    float* s_hb1  = sm + 18432;
    float* s_hw2  = sm + 18720;
    float* s_hb2  = sm + 19008;
    float* s_free = sm + 19072;
    for (int i = tid; i < 18432 / 4; i += 384) ((float4*)s_hw1)[i] = ((const float4*)Wh1)[i];
    if (tid < 288) { s_hb1[tid] = bh1[tid]; s_hw2[tid] = Wh2[tid]; }
    if (tid >= 288 && tid < 297) s_hb2[tid - 288] = bh2[tid - 288];
    if (tid >= 320 && tid < 343) s_free[tid - 320] = 0.0f;
    __syncthreads();

    if (valid && s < NKNOWN) {
        int k = s;
        float ha[32];
        #pragma unroll
        for (int h = 0; h < 32; h++) ha[h] = s_hb1[k * 32 + h];
        #pragma unroll 2
        for (int d = 0; d < 64; d++) {
            float p = s_prev[pbase + d];
            const float4* w = (const float4*)(s_hw1 + k * 2048 + d * 32);
            #pragma unroll
            for (int q = 0; q < 8; q++) {
                float4 a = w[q];
                ha[4 * q + 0] += p * a.x; ha[4 * q + 1] += p * a.y;
                ha[4 * q + 2] += p * a.z; ha[4 * q + 3] += p * a.w;
            }
        }
        float a2 = s_hb2[k];
        #pragma unroll
        for (int h = 0; h < 32; h++) a2 += gelu_f(ha[h]) * s_hw2[k * 32 + h];
        out[PV_OFF + b * NKNOWN + k] = sigm_f(a2);   // exact sigmoid at the head
    } else if (valid && s >= NKNOWN) {
        atomicAdd(s_free + (s - NKNOWN), freeval);
    }
    __syncthreads();
    if (tid < NSLOT - NKNOWN) atomicAdd(out + FREE_OFF + tid, s_free[tid]);
}

// ================= launch =================
extern "C" void kernel_launch(void* const* d_in, const int* in_sizes, int n_in,
                              void* d_out, int out_size)
{
    const float* ws   = (const float*)d_in[0];
    const float* eps  = (const float*)d_in[1];
    const float* mu0  = (const float*)d_in[2];
    const float* sg0  = (const float*)d_in[3];
    const float* Wi   = (const float*)d_in[4];
    const float* bi   = (const float*)d_in[5];
    // d_in[6..9] = Wk, bk, Wq, bq : dead (attn == 1.0 exactly)
    const float* Wv   = (const float*)d_in[10];
    const float* bv   = (const float*)d_in[11];
    const float* Wih  = (const float*)d_in[12];
    const float* bih  = (const float*)d_in[13];
    const float* Whh  = (const float*)d_in[14];
    const float* bhh  = (const float*)d_in[15];
    const float* W1   = (const float*)d_in[16];
    const float* b1   = (const float*)d_in[17];
    const float* W2   = (const float*)d_in[18];
    const float* b2   = (const float*)d_in[19];
    const float* g_in = (const float*)d_in[20];
    const float* b_in = (const float*)d_in[21];
    // d_in[22..23] = g_sl, b_sl : dead
    const float* gm   = (const float*)d_in[24];
    const float* bm   = (const float*)d_in[25];
    const float* Wh1  = (const float*)d_in[26];
    const float* bh1  = (const float*)d_in[27];
    const float* Wh2  = (const float*)d_in[28];
    const float* bh2  = (const float*)d_in[29];
    float* out = (float*)d_out;

    size_t smemA = (size_t)SMEMA_FLOATS * sizeof(float);
    size_t smemB = (size_t)SMEMB_FLOATS * sizeof(float);
    cudaFuncSetAttribute(kA2, cudaFuncAttributeMaxDynamicSharedMemorySize, (int)smemA);
    cudaFuncSetAttribute(kB,  cudaFuncAttributeMaxDynamicSharedMemorySize, (int)smemB);

    int gridB = (B_TOTAL + GROUPS_B - 1) / GROUPS_B;   // 1366
    kA2<<<B_TOTAL / 8, 512, smemA>>>(ws, Wi, bi, g_in, b_in, Wv, bv, Wih, bih);
    kZ<<<1, 32>>>(out);
    kB<<<gridB, 384, smemB>>>(eps, mu0, sg0, Whh, bhh, W1, b1, W2, b2,
                              gm, bm, Wh1, bh1, Wh2, bh2, out);
}